// round 16
// baseline (speedup 1.0000x reference)
#include <cuda_runtime.h>
#include <cuda_fp16.h>
#include <cstdint>

#define B_    512
#define C_    20000
#define DE    512
#define KD    2048          // K * Dp = 8 * 256
#define TEMP  0.07f
#define MOM   0.999f
#define NHN   16
#define BSCALE 64.0f        // proto pre-scale so fp16 lo-residuals stay normal
#define BINV   (1.0f / 64.0f)

#define NCHUNK  8           // K chunks of 64 fp16 cols
#define CHUNK_B 16384       // 128 rows x 128 B per (tile, chunk) block
#define NTILE_C 157         // class tiles of 128 (last padded with zeros)

// embedded part-bank copy
#define PBYTES  163840000LL // 40,960,000 floats
#define CPYB    14336       // staging chunk bytes (multiple of 16)
#define NCPY    19          // chunks per CTA (628*19 = 11932 >= 11429)

// ---------------- scratch (device globals: allocation-free) ----------------
__device__ float g_sim[(size_t)B_ * C_];                 // 41 MB
__device__ float g_invp[C_];
__device__ float g_nce[B_];
__device__ float g_align[B_];
__device__ int   g_lab[B_];
__device__ int   g_invmap[C_];                           // class -> batch row (or -1)
// operand arrays in tiled + SW128-swizzled layout: [tile][chunk][16KB block]
__device__ __align__(128) __half g_qh[B_ * DE];                    // 4 tiles
__device__ __align__(128) __half g_ph[(size_t)NTILE_C * 128 * DE]; // 157 tiles (pad=0)
__device__ __align__(128) __half g_pl[(size_t)NTILE_C * 128 * DE];

__device__ __forceinline__ size_t tco(int tile, int ck) {   // block byte offset
    return ((size_t)tile * NCHUNK + ck) * CHUNK_B;
}
__device__ __forceinline__ uint32_t sw128(uint32_t b) { return b ^ ((b >> 3) & 0x70); }

// ---------------- helpers ----------------
__device__ __forceinline__ uint32_t pack_h2(float a, float b) {
    __half2 h = __floats2half2_rn(a, b);   // a -> low 16 bits
    return *reinterpret_cast<uint32_t*>(&h);
}

// ---------------- 0a: clear inverse label map ----------------
__global__ void clear_invmap() {
    int i = blockIdx.x * blockDim.x + threadIdx.x;
    if (i < C_) g_invmap[i] = -1;
}

// ---------------- 0b: decode labels + scatter inverse map ----------------
__global__ void decode_labels(const int* __restrict__ raw) {
    __shared__ int is64;
    if (threadIdx.x == 0) {
        int odd_or = 0;
        for (int i = 1; i < 64; i += 2) odd_or |= raw[i];
        is64 = (odd_or == 0) ? 1 : 0;
    }
    __syncthreads();
    int t = threadIdx.x;           // 512 threads
    int v = is64 ? raw[2 * t] : raw[t];
    if (v < 0) v = 0;
    if (v >= C_) v = C_ - 1;
    g_lab[t] = v;
    g_invmap[v] = t;               // labels distinct -> no conflicts
}

// ---------------- 2: EMA fix-up on labeled part-bank rows (after GEMM copy) -
__global__ void ema_part(const float* __restrict__ pf, const float* __restrict__ pb,
                         float* __restrict__ opb) {
    int b = blockIdx.x;
    int lab = g_lab[b];
    const float om = 1.0f - MOM;
    const float* src_p = pf + (size_t)b * KD;
    const float* old_p = pb + (size_t)lab * KD;
    float*       dst_p = opb + (size_t)lab * KD;
    for (int i = threadIdx.x; i < KD; i += blockDim.x)
        dst_p[i] = MOM * old_p[i] + om * src_p[i];
}

// ---------------- tiled+swizzled 8B store helper ----------------
__device__ __forceinline__ void store_tiled(__half* base, int tile, int rl, int c0,
                                            uint2 val) {
    const int ck = c0 >> 6;                    // 64 cols per chunk
    const int cc = c0 & 63;
    uint32_t b = (uint32_t)(rl * 128 + cc * 2);
    *(uint2*)((char*)base + tco(tile, ck) + sw128(b)) = val;
}

// ---------------- 3: fused proto prep + q prep (fp16 split, tiled out) ------
__global__ void proto_fused(const float* __restrict__ ebk, const float* __restrict__ emb,
                            float* __restrict__ oeb) {
    int w = (blockIdx.x * blockDim.x + threadIdx.x) >> 5;
    int lane = threadIdx.x & 31;
    if (w < C_) {
        const int inv = g_invmap[w];
        const float4* r = (const float4*)(ebk + (size_t)w * DE);
        float4 v[4];
#pragma unroll
        for (int i = 0; i < 4; i++) v[i] = r[lane + 32 * i];
        if (inv >= 0) {
            const float4* e = (const float4*)(emb + (size_t)inv * DE);
            const float om = 1.0f - MOM;
#pragma unroll
            for (int i = 0; i < 4; i++) {
                float4 ev = e[lane + 32 * i];
                v[i].x = MOM * v[i].x + om * ev.x;
                v[i].y = MOM * v[i].y + om * ev.y;
                v[i].z = MOM * v[i].z + om * ev.z;
                v[i].w = MOM * v[i].w + om * ev.w;
            }
        }
        float s = 0.0f;
#pragma unroll
        for (int i = 0; i < 4; i++)
            s += v[i].x * v[i].x + v[i].y * v[i].y + v[i].z * v[i].z + v[i].w * v[i].w;
#pragma unroll
        for (int o = 16; o; o >>= 1) s += __shfl_xor_sync(0xffffffffu, s, o);
        if (lane == 0) g_invp[w] = 1.0f / fmaxf(sqrtf(s), 1e-12f);

        float4* ob = (float4*)(oeb + (size_t)w * DE);
        const int tile = w >> 7, rl = w & 127;
#pragma unroll
        for (int i = 0; i < 4; i++) {
            ob[lane + 32 * i] = v[i];
            float4 x = v[i];
            x.x *= BSCALE; x.y *= BSCALE; x.z *= BSCALE; x.w *= BSCALE;
            __half hx = __float2half_rn(x.x), hy = __float2half_rn(x.y);
            __half hz = __float2half_rn(x.z), hw = __float2half_rn(x.w);
            uint2 uh, ul;
            uh.x = (uint32_t)__half_as_ushort(hx) | ((uint32_t)__half_as_ushort(hy) << 16);
            uh.y = (uint32_t)__half_as_ushort(hz) | ((uint32_t)__half_as_ushort(hw) << 16);
            ul.x = pack_h2(x.x - __half2float(hx), x.y - __half2float(hy));
            ul.y = pack_h2(x.z - __half2float(hz), x.w - __half2float(hw));
            const int c0 = 4 * (lane + 32 * i);
            store_tiled(g_ph, tile, rl, c0, uh);
            store_tiled(g_pl, tile, rl, c0, ul);
        }
    } else if (w < C_ + B_) {
        const int b = w - C_;
        const float4* r = (const float4*)(emb + (size_t)b * DE);
        float4 v[4];
        float s = 0.0f;
#pragma unroll
        for (int i = 0; i < 4; i++) {
            v[i] = r[lane + 32 * i];
            s += v[i].x * v[i].x + v[i].y * v[i].y + v[i].z * v[i].z + v[i].w * v[i].w;
        }
#pragma unroll
        for (int o = 16; o; o >>= 1) s += __shfl_xor_sync(0xffffffffu, s, o);
        float inv = 1.0f / (fmaxf(sqrtf(s), 1e-12f) * TEMP);
        const int tile = b >> 7, rl = b & 127;
#pragma unroll
        for (int i = 0; i < 4; i++) {
            float4 x = v[i];
            x.x *= inv; x.y *= inv; x.z *= inv; x.w *= inv;
            __half hx = __float2half_rn(x.x), hy = __float2half_rn(x.y);
            __half hz = __float2half_rn(x.z), hw = __float2half_rn(x.w);
            uint2 uh;
            uh.x = (uint32_t)__half_as_ushort(hx) | ((uint32_t)__half_as_ushort(hy) << 16);
            uh.y = (uint32_t)__half_as_ushort(hz) | ((uint32_t)__half_as_ushort(hw) << 16);
            store_tiled(g_qh, tile, rl, 4 * (lane + 32 * i), uh);
        }
    }
}

// ---------------- 5: GEMM + warp-specialized part-bank copy ----------------
#define STAGE_B (3 * CHUNK_B)                           // 49152 B (Ah, Bh, Bl)
#define STG_OFF (128 + 2 * STAGE_B)                     // staging buffer offset
#define GEMM_SMEM (128 + 2 * STAGE_B + CPYB)            // 112,768 B -> 2 CTAs/SM

#define LDSM4(r0, r1, r2, r3, addr) \
    asm volatile("ldmatrix.sync.aligned.m8n8.x4.shared.b16 {%0,%1,%2,%3}, [%4];" \
                 : "=r"(r0), "=r"(r1), "=r"(r2), "=r"(r3) : "r"(addr))

#define MMAF16(d, a, b0v, b1v) \
    asm volatile("mma.sync.aligned.m16n8k16.row.col.f32.f16.f16.f32 " \
                 "{%0,%1,%2,%3}, {%4,%5,%6,%7}, {%8,%9}, {%0,%1,%2,%3};" \
                 : "+f"(d.x), "+f"(d.y), "+f"(d.z), "+f"(d.w) \
                 : "r"(a[0]), "r"(a[1]), "r"(a[2]), "r"(a[3]), "r"(b0v), "r"(b1v))

#define BAR_MMA() asm volatile("bar.sync 1, 256;" ::: "memory")

__device__ __forceinline__ void bulk_g2s(uint32_t dst, const void* src, uint32_t bytes,
                                         uint32_t mbar) {
    asm volatile(
        "cp.async.bulk.shared::cta.global.mbarrier::complete_tx::bytes [%0], [%1], %2, [%3];"
        :: "r"(dst), "l"(src), "r"(bytes), "r"(mbar) : "memory");
}
__device__ __forceinline__ void bulk_s2g(void* dst, uint32_t src, uint32_t bytes) {
    asm volatile("cp.async.bulk.global.shared::cta.bulk_group [%0], [%1], %2;"
                 :: "l"(dst), "r"(src), "r"(bytes) : "memory");
}
__device__ __forceinline__ void mbar_expect(uint32_t mbar, uint32_t bytes) {
    asm volatile("mbarrier.arrive.expect_tx.shared.b64 _, [%0], %1;"
                 :: "r"(mbar), "r"(bytes) : "memory");
}
__device__ __forceinline__ void mbar_wait(uint32_t mbar, uint32_t phase) {
    uint32_t done = 0;
    while (!done)
        asm volatile("{\n\t.reg .pred p;\n\t"
                     "mbarrier.try_wait.parity.acquire.cta.shared::cta.b64 p, [%1], %2;\n\t"
                     "selp.b32 %0, 1, 0, p;\n\t}"
                     : "=r"(done) : "r"(mbar), "r"(phase) : "memory");
}

__global__ __launch_bounds__(288, 2)
void sim_gemm_tc(const char* __restrict__ cp_src, char* __restrict__ cp_dst) {
    extern __shared__ __align__(128) char smem[];
    const uint32_t sbase = (uint32_t)__cvta_generic_to_shared(smem);
    const uint32_t sb = sbase + 128;             // operand stages

    const int tid  = threadIdx.x;
    const int lane = tid & 31;
    const int by = blockIdx.y;                   // batch tile (0..3)
    const int bx = blockIdx.x;                   // class tile (0..156)

    if (tid == 0) {
        asm volatile("mbarrier.init.shared.b64 [%0], 1;" :: "r"(sbase) : "memory");
        asm volatile("mbarrier.init.shared.b64 [%0], 1;" :: "r"(sbase + 8) : "memory");
        asm volatile("mbarrier.init.shared.b64 [%0], 1;" :: "r"(sbase + 16) : "memory");
    }
    __syncthreads();                             // all 288 threads

    if (tid < 256) {
        // ================= compute warps 0-7 (R15-proven body) =================
        const int wid  = tid >> 5;
        const int wm   = wid & 1;
        const int wn   = wid >> 1;
        const int m_base = wm * 64;
        const int n_base = wn * 32;
        const int row0 = by * 128;
        const int col0 = bx * 128;

        const char* srcA  = (const char*)g_qh;
        const char* srcBh = (const char*)g_ph;
        const char* srcBl = (const char*)g_pl;

        auto fill = [&](int s, int ck) {
            const uint32_t mb = sbase + s * 8;
            const uint32_t d  = sb + s * STAGE_B;
            mbar_expect(mb, STAGE_B);
            bulk_g2s(d,               srcA  + tco(by, ck), CHUNK_B, mb);
            bulk_g2s(d + CHUNK_B,     srcBh + tco(bx, ck), CHUNK_B, mb);
            bulk_g2s(d + 2 * CHUNK_B, srcBl + tco(bx, ck), CHUNK_B, mb);
        };

        if (tid == 0) { fill(0, 0); fill(1, 1); }

        const int rA = (lane & 7) + ((lane >> 3) & 1) * 8;
        const int hA = ((lane >> 4) & 1) * 16;
        const int rB = (lane & 7) + ((lane >> 4) & 1) * 8;
        const int hB = ((lane >> 3) & 1) * 16;

        float4 acc[4][4];
#pragma unroll
        for (int i = 0; i < 4; i++)
#pragma unroll
            for (int j = 0; j < 4; j++) acc[i][j] = make_float4(0.f, 0.f, 0.f, 0.f);

        for (int kt = 0; kt < NCHUNK; kt++) {
            const int s = kt & 1;
            mbar_wait(sbase + s * 8, (kt >> 1) & 1);

            const uint32_t bAh = sb + s * STAGE_B;
            const uint32_t bBh = bAh + CHUNK_B;
            const uint32_t bBl = bAh + 2 * CHUNK_B;
#pragma unroll
            for (int kk = 0; kk < 4; kk++) {
                uint32_t Ah[4][4], Bh[2][4], Bl[2][4];
#pragma unroll
                for (int im = 0; im < 4; im++) {
                    uint32_t b = (uint32_t)((m_base + im * 16 + rA) * 128 + kk * 32 + hA);
                    LDSM4(Ah[im][0], Ah[im][1], Ah[im][2], Ah[im][3], bAh + sw128(b));
                }
#pragma unroll
                for (int t2 = 0; t2 < 2; t2++) {
                    uint32_t b = (uint32_t)((n_base + t2 * 16 + rB) * 128 + kk * 32 + hB);
                    LDSM4(Bh[t2][0], Bh[t2][1], Bh[t2][2], Bh[t2][3], bBh + sw128(b));
                    LDSM4(Bl[t2][0], Bl[t2][1], Bl[t2][2], Bl[t2][3], bBl + sw128(b));
                }
#pragma unroll
                for (int im = 0; im < 4; im++)
#pragma unroll
                    for (int in = 0; in < 4; in++)
                        MMAF16(acc[im][in], Ah[im], Bh[in >> 1][(in & 1) * 2],
                               Bh[in >> 1][(in & 1) * 2 + 1]);
#pragma unroll
                for (int im = 0; im < 4; im++)
#pragma unroll
                    for (int in = 0; in < 4; in++)
                        MMAF16(acc[im][in], Ah[im], Bl[in >> 1][(in & 1) * 2],
                               Bl[in >> 1][(in & 1) * 2 + 1]);
            }
            BAR_MMA();                            // compute warps done with stage s
            if (tid == 0 && kt + 2 < NCHUNK) fill(s, kt + 2);
        }

        // epilogue: scale by invp[col]/64, write g_sim
        const int gq = lane >> 2;
        const int qp = (lane & 3) * 2;
#pragma unroll
        for (int im = 0; im < 4; im++) {
            const int r = row0 + m_base + im * 16 + gq;
            float* row_ptr0 = g_sim + (size_t)r * C_;
            float* row_ptr1 = g_sim + (size_t)(r + 8) * C_;
#pragma unroll
            for (int in = 0; in < 4; in++) {
                const int c = col0 + n_base + in * 8 + qp;
                if (c < C_) {
                    const float ip0 = g_invp[c] * BINV;
                    const float ip1 = g_invp[c + 1] * BINV;
                    float4 a = acc[im][in];
                    float2 lo = make_float2(a.x * ip0, a.y * ip1);
                    float2 hi = make_float2(a.z * ip0, a.w * ip1);
                    *(float2*)(row_ptr0 + c) = lo;
                    *(float2*)(row_ptr1 + c) = hi;
                }
            }
        }
        BAR_MMA();
        if (tid == 0) {
            asm volatile("mbarrier.inval.shared.b64 [%0];" :: "r"(sbase) : "memory");
            asm volatile("mbarrier.inval.shared.b64 [%0];" :: "r"(sbase + 8) : "memory");
        }
    } else if (tid == 256) {
        // ================= copy warp: stream part bank through smem =============
        const uint32_t mc  = sbase + 16;
        const uint32_t stg = sbase + STG_OFF;
        const int cta = by * gridDim.x + bx;     // 0..627
        long long j0 = (long long)cta * NCPY;
        uint32_t phase = 0;
        for (int i = 0; i < NCPY; i++) {
            long long off = (j0 + i) * (long long)CPYB;
            if (off >= PBYTES) break;
            uint32_t bytes = (uint32_t)((PBYTES - off < (long long)CPYB)
                                        ? (PBYTES - off) : CPYB);
            mbar_expect(mc, bytes);
            bulk_g2s(stg, cp_src + off, bytes, mc);
            mbar_wait(mc, phase); phase ^= 1;
            bulk_s2g(cp_dst + off, stg, bytes);
            asm volatile("cp.async.bulk.commit_group;" ::: "memory");
            asm volatile("cp.async.bulk.wait_group 0;" ::: "memory");
        }
        asm volatile("mbarrier.inval.shared.b64 [%0];" :: "r"(mc) : "memory");
    }
}

// ---------------- 6: top-16 negatives + logsumexp per row ----------------
__global__ __launch_bounds__(256)
void topk_lse() {
    __shared__ float cand[256 * NHN];
    const int b = blockIdx.x;
    const int tid = threadIdx.x;
    const int lab = g_lab[b];
    const float* row = g_sim + (size_t)b * C_;

    float lt[NHN];
#pragma unroll
    for (int i = 0; i < NHN; i++) lt[i] = -1e30f;

    const float4* row4 = (const float4*)row;
    for (int c4 = tid; c4 < C_ / 4; c4 += 256) {
        float4 v4 = row4[c4];
        const int cb = c4 * 4;
        float vv[4] = {v4.x, v4.y, v4.z, v4.w};
#pragma unroll
        for (int j = 0; j < 4; j++) {
            if (cb + j == lab) continue;
            float v = vv[j];
            if (v > lt[NHN - 1]) {
                int k = NHN - 1;
                while (k > 0 && lt[k - 1] < v) { lt[k] = lt[k - 1]; --k; }
                lt[k] = v;
            }
        }
    }
#pragma unroll
    for (int i = 0; i < NHN; i++) cand[tid * NHN + i] = lt[i];

    for (int s = 128; s >= 1; s >>= 1) {
        __syncthreads();
        if (tid < s) {
            const float* Aa = cand + tid * NHN;
            const float* Bb = cand + (tid + s) * NHN;
            float out[NHN];
            int i = 0, j = 0;
#pragma unroll
            for (int t = 0; t < NHN; t++) {
                float a = Aa[i], bv = Bb[j];
                if (a >= bv) { out[t] = a; i++; } else { out[t] = bv; j++; }
            }
#pragma unroll
            for (int t = 0; t < NHN; t++) cand[tid * NHN + t] = out[t];
        }
    }
    __syncthreads();
    if (tid == 0) {
        float pos = row[lab];
        float mx = pos;
#pragma unroll
        for (int i = 0; i < NHN; i++) mx = fmaxf(mx, cand[i]);
        float sum = __expf(pos - mx);
#pragma unroll
        for (int i = 0; i < NHN; i++) sum += __expf(cand[i] - mx);
        g_nce[b] = mx + logf(sum) - pos;
    }
}

// ---------------- 7: alignment loss per row ----------------
__global__ __launch_bounds__(256)
void align_row(const float* __restrict__ emb, const float* __restrict__ sat,
               const float* __restrict__ neb) {
    __shared__ float red[5][8];
    const int b = blockIdx.x;
    const int tid = threadIdx.x;
    const int lab = g_lab[b];
    const float* e = emb + (size_t)b * DE;
    const float* s = sat + (size_t)b * DE;
    const float* p = neb + (size_t)lab * DE;
    float ee = 0, ss = 0, pp = 0, ep = 0, sp = 0;
    for (int i = tid; i < DE; i += 256) {
        float ev = e[i], sv = s[i], pv = p[i];
        ee += ev * ev; ss += sv * sv; pp += pv * pv;
        ep += ev * pv; sp += sv * pv;
    }
#pragma unroll
    for (int o = 16; o; o >>= 1) {
        ee += __shfl_xor_sync(0xffffffffu, ee, o);
        ss += __shfl_xor_sync(0xffffffffu, ss, o);
        pp += __shfl_xor_sync(0xffffffffu, pp, o);
        ep += __shfl_xor_sync(0xffffffffu, ep, o);
        sp += __shfl_xor_sync(0xffffffffu, sp, o);
    }
    int w = tid >> 5;
    if ((tid & 31) == 0) {
        red[0][w] = ee; red[1][w] = ss; red[2][w] = pp; red[3][w] = ep; red[4][w] = sp;
    }
    __syncthreads();
    if (tid == 0) {
        float a0 = 0, a1 = 0, a2 = 0, a3 = 0, a4 = 0;
        for (int i = 0; i < 8; i++) {
            a0 += red[0][i]; a1 += red[1][i]; a2 += red[2][i];
            a3 += red[3][i]; a4 += red[4][i];
        }
        float dn = fmaxf(sqrtf(a0), 1e-12f);
        float sn = fmaxf(sqrtf(a1), 1e-12f);
        float pn = fmaxf(sqrtf(a2), 1e-12f);
        g_align[b] = 0.5f * ((1.0f - a3 / (dn * pn)) + (1.0f - a4 / (sn * pn)));
    }
}

// ---------------- 8: final scalar reduction ----------------
__global__ __launch_bounds__(512)
void finalize(float* __restrict__ out_loss) {
    __shared__ float s1[512], s2[512];
    int t = threadIdx.x;
    s1[t] = g_nce[t];
    s2[t] = g_align[t];
    __syncthreads();
    for (int s = 256; s >= 1; s >>= 1) {
        if (t < s) { s1[t] += s1[t + s]; s2[t] += s2[t + s]; }
        __syncthreads();
    }
    if (t == 0) {
        out_loss[0] = s1[0] / (float)B_;
        out_loss[1] = s2[0] / (float)B_;
    }
}

// ---------------- launch ----------------
extern "C" void kernel_launch(void* const* d_in, const int* in_sizes, int n_in,
                              void* d_out, int out_size) {
    const float* pf    = (const float*)d_in[0];     // [512, 8, 256]
    const float* emb   = (const float*)d_in[1];     // [512, 512]
    const float* sat   = (const float*)d_in[2];     // [512, 512]
    const float* pbank = (const float*)d_in[3];     // [20000, 8, 256]
    const float* ebank = (const float*)d_in[4];     // [20000, 512]
    const int*   labs  = (const int*)d_in[5];       // [512] int32/int64 auto-detected

    const int P = in_sizes[3];   // 40,960,000
    const int E = in_sizes[4];   // 10,240,000

    float* out    = (float*)d_out;
    float* out_pb = out;
    float* out_eb = out + P;
    float* out_ls = out + P + E;

    static bool attr_done = false;
    if (!attr_done) {
        cudaFuncSetAttribute(sim_gemm_tc,
                             cudaFuncAttributeMaxDynamicSharedMemorySize, GEMM_SMEM);
        attr_done = true;
    }

    // 0. labels + inverse map
    clear_invmap<<<(C_ + 255) / 256, 256>>>();
    decode_labels<<<1, B_>>>(labs);
    // 1. fused embed copy + EMA + norms + fp16 splits (tiled layout) + q prep
    proto_fused<<<(C_ + B_ + 7) / 8, 256>>>(ebank, emb, out_eb);
    // 2. GEMM with warp-specialized part-bank copy (raw copy embedded)
    dim3 ggrid(NTILE_C, B_ / 128);
    sim_gemm_tc<<<ggrid, 288, GEMM_SMEM>>>((const char*)pbank, (char*)out_pb);
    // 3. EMA fix-up on the 512 labeled part rows
    ema_part<<<B_, 256>>>(pf, pbank, out_pb);
    // 4. top-k + logsumexp
    topk_lse<<<B_, 256>>>();
    // 5. alignment
    align_row<<<B_, 256>>>(emb, sat, out_eb);
    // 6. finalize scalars
    finalize<<<1, 512>>>(out_ls);
}

// round 17
// speedup vs baseline: 1.0511x; 1.0511x over previous
#include <cuda_runtime.h>
#include <cuda_fp16.h>
#include <cstdint>

#define B_    512
#define C_    20000
#define DE    512
#define KD    2048          // K * Dp = 8 * 256
#define TEMP  0.07f
#define MOM   0.999f
#define NHN   16
#define BSCALE 64.0f        // proto pre-scale so fp16 lo-residuals stay normal
#define BINV   (1.0f / 64.0f)

#define NCHUNK  8           // K chunks of 64 fp16 cols
#define CHUNK_B 16384       // 128 rows x 128 B per (tile, chunk) block
#define NTILE_C 157         // class tiles of 128 (last padded with zeros)

// embedded part-bank copy (pipelined, 4 staging buffers)
#define PBYTES  163840000LL // 40,960,000 floats = 40000 x 4096 exactly
#define CPYB    4096        // staging chunk bytes
#define NSTG    4           // staging buffers (prefetch distance 2)
#define NCPY    64          // chunks per CTA (628*64 = 40192 >= 40000)

// ---------------- scratch (device globals: allocation-free) ----------------
__device__ float g_sim[(size_t)B_ * C_];                 // 41 MB
__device__ float g_invp[C_];
__device__ float g_nce[B_];
__device__ float g_align[B_];
__device__ int   g_lab[B_];
__device__ int   g_invmap[C_];                           // class -> batch row (or -1)
// operand arrays in tiled + SW128-swizzled layout: [tile][chunk][16KB block]
__device__ __align__(128) __half g_qh[B_ * DE];                    // 4 tiles
__device__ __align__(128) __half g_ph[(size_t)NTILE_C * 128 * DE]; // 157 tiles (pad=0)
__device__ __align__(128) __half g_pl[(size_t)NTILE_C * 128 * DE];

__device__ __forceinline__ size_t tco(int tile, int ck) {   // block byte offset
    return ((size_t)tile * NCHUNK + ck) * CHUNK_B;
}
__device__ __forceinline__ uint32_t sw128(uint32_t b) { return b ^ ((b >> 3) & 0x70); }

// ---------------- helpers ----------------
__device__ __forceinline__ uint32_t pack_h2(float a, float b) {
    __half2 h = __floats2half2_rn(a, b);   // a -> low 16 bits
    return *reinterpret_cast<uint32_t*>(&h);
}

// ---------------- 0a: clear inverse label map ----------------
__global__ void clear_invmap() {
    int i = blockIdx.x * blockDim.x + threadIdx.x;
    if (i < C_) g_invmap[i] = -1;
}

// ---------------- 0b: decode labels + scatter inverse map ----------------
__global__ void decode_labels(const int* __restrict__ raw) {
    __shared__ int is64;
    if (threadIdx.x == 0) {
        int odd_or = 0;
        for (int i = 1; i < 64; i += 2) odd_or |= raw[i];
        is64 = (odd_or == 0) ? 1 : 0;
    }
    __syncthreads();
    int t = threadIdx.x;           // 512 threads
    int v = is64 ? raw[2 * t] : raw[t];
    if (v < 0) v = 0;
    if (v >= C_) v = C_ - 1;
    g_lab[t] = v;
    g_invmap[v] = t;               // labels distinct -> no conflicts
}

// ---------------- 2: EMA fix-up on labeled part-bank rows (after GEMM copy) -
__global__ void ema_part(const float* __restrict__ pf, const float* __restrict__ pb,
                         float* __restrict__ opb) {
    int b = blockIdx.x;
    int lab = g_lab[b];
    const float om = 1.0f - MOM;
    const float* src_p = pf + (size_t)b * KD;
    const float* old_p = pb + (size_t)lab * KD;
    float*       dst_p = opb + (size_t)lab * KD;
    for (int i = threadIdx.x; i < KD; i += blockDim.x)
        dst_p[i] = MOM * old_p[i] + om * src_p[i];
}

// ---------------- tiled+swizzled 8B store helper ----------------
__device__ __forceinline__ void store_tiled(__half* base, int tile, int rl, int c0,
                                            uint2 val) {
    const int ck = c0 >> 6;                    // 64 cols per chunk
    const int cc = c0 & 63;
    uint32_t b = (uint32_t)(rl * 128 + cc * 2);
    *(uint2*)((char*)base + tco(tile, ck) + sw128(b)) = val;
}

// ---------------- 3: fused proto prep + q prep (fp16 split, tiled out) ------
__global__ void proto_fused(const float* __restrict__ ebk, const float* __restrict__ emb,
                            float* __restrict__ oeb) {
    int w = (blockIdx.x * blockDim.x + threadIdx.x) >> 5;
    int lane = threadIdx.x & 31;
    if (w < C_) {
        const int inv = g_invmap[w];
        const float4* r = (const float4*)(ebk + (size_t)w * DE);
        float4 v[4];
#pragma unroll
        for (int i = 0; i < 4; i++) v[i] = r[lane + 32 * i];
        if (inv >= 0) {
            const float4* e = (const float4*)(emb + (size_t)inv * DE);
            const float om = 1.0f - MOM;
#pragma unroll
            for (int i = 0; i < 4; i++) {
                float4 ev = e[lane + 32 * i];
                v[i].x = MOM * v[i].x + om * ev.x;
                v[i].y = MOM * v[i].y + om * ev.y;
                v[i].z = MOM * v[i].z + om * ev.z;
                v[i].w = MOM * v[i].w + om * ev.w;
            }
        }
        float s = 0.0f;
#pragma unroll
        for (int i = 0; i < 4; i++)
            s += v[i].x * v[i].x + v[i].y * v[i].y + v[i].z * v[i].z + v[i].w * v[i].w;
#pragma unroll
        for (int o = 16; o; o >>= 1) s += __shfl_xor_sync(0xffffffffu, s, o);
        if (lane == 0) g_invp[w] = 1.0f / fmaxf(sqrtf(s), 1e-12f);

        float4* ob = (float4*)(oeb + (size_t)w * DE);
        const int tile = w >> 7, rl = w & 127;
#pragma unroll
        for (int i = 0; i < 4; i++) {
            ob[lane + 32 * i] = v[i];
            float4 x = v[i];
            x.x *= BSCALE; x.y *= BSCALE; x.z *= BSCALE; x.w *= BSCALE;
            __half hx = __float2half_rn(x.x), hy = __float2half_rn(x.y);
            __half hz = __float2half_rn(x.z), hw = __float2half_rn(x.w);
            uint2 uh, ul;
            uh.x = (uint32_t)__half_as_ushort(hx) | ((uint32_t)__half_as_ushort(hy) << 16);
            uh.y = (uint32_t)__half_as_ushort(hz) | ((uint32_t)__half_as_ushort(hw) << 16);
            ul.x = pack_h2(x.x - __half2float(hx), x.y - __half2float(hy));
            ul.y = pack_h2(x.z - __half2float(hz), x.w - __half2float(hw));
            const int c0 = 4 * (lane + 32 * i);
            store_tiled(g_ph, tile, rl, c0, uh);
            store_tiled(g_pl, tile, rl, c0, ul);
        }
    } else if (w < C_ + B_) {
        const int b = w - C_;
        const float4* r = (const float4*)(emb + (size_t)b * DE);
        float4 v[4];
        float s = 0.0f;
#pragma unroll
        for (int i = 0; i < 4; i++) {
            v[i] = r[lane + 32 * i];
            s += v[i].x * v[i].x + v[i].y * v[i].y + v[i].z * v[i].z + v[i].w * v[i].w;
        }
#pragma unroll
        for (int o = 16; o; o >>= 1) s += __shfl_xor_sync(0xffffffffu, s, o);
        float inv = 1.0f / (fmaxf(sqrtf(s), 1e-12f) * TEMP);
        const int tile = b >> 7, rl = b & 127;
#pragma unroll
        for (int i = 0; i < 4; i++) {
            float4 x = v[i];
            x.x *= inv; x.y *= inv; x.z *= inv; x.w *= inv;
            __half hx = __float2half_rn(x.x), hy = __float2half_rn(x.y);
            __half hz = __float2half_rn(x.z), hw = __float2half_rn(x.w);
            uint2 uh;
            uh.x = (uint32_t)__half_as_ushort(hx) | ((uint32_t)__half_as_ushort(hy) << 16);
            uh.y = (uint32_t)__half_as_ushort(hz) | ((uint32_t)__half_as_ushort(hw) << 16);
            store_tiled(g_qh, tile, rl, 4 * (lane + 32 * i), uh);
        }
    }
}

// ---------------- 5: GEMM + pipelined warp-specialized part-bank copy -------
#define STAGE_B (3 * CHUNK_B)                           // 49152 B (Ah, Bh, Bl)
#define STG_OFF (128 + 2 * STAGE_B)                     // staging buffers offset
#define GEMM_SMEM (128 + 2 * STAGE_B + NSTG * CPYB)     // 114,816 B -> 2 CTAs/SM

#define LDSM4(r0, r1, r2, r3, addr) \
    asm volatile("ldmatrix.sync.aligned.m8n8.x4.shared.b16 {%0,%1,%2,%3}, [%4];" \
                 : "=r"(r0), "=r"(r1), "=r"(r2), "=r"(r3) : "r"(addr))

#define MMAF16(d, a, b0v, b1v) \
    asm volatile("mma.sync.aligned.m16n8k16.row.col.f32.f16.f16.f32 " \
                 "{%0,%1,%2,%3}, {%4,%5,%6,%7}, {%8,%9}, {%0,%1,%2,%3};" \
                 : "+f"(d.x), "+f"(d.y), "+f"(d.z), "+f"(d.w) \
                 : "r"(a[0]), "r"(a[1]), "r"(a[2]), "r"(a[3]), "r"(b0v), "r"(b1v))

#define BAR_MMA() asm volatile("bar.sync 1, 256;" ::: "memory")

__device__ __forceinline__ void bulk_g2s(uint32_t dst, const void* src, uint32_t bytes,
                                         uint32_t mbar) {
    asm volatile(
        "cp.async.bulk.shared::cta.global.mbarrier::complete_tx::bytes [%0], [%1], %2, [%3];"
        :: "r"(dst), "l"(src), "r"(bytes), "r"(mbar) : "memory");
}
__device__ __forceinline__ void bulk_s2g(void* dst, uint32_t src, uint32_t bytes) {
    asm volatile("cp.async.bulk.global.shared::cta.bulk_group [%0], [%1], %2;"
                 :: "l"(dst), "r"(src), "r"(bytes) : "memory");
}
__device__ __forceinline__ void mbar_expect(uint32_t mbar, uint32_t bytes) {
    asm volatile("mbarrier.arrive.expect_tx.shared.b64 _, [%0], %1;"
                 :: "r"(mbar), "r"(bytes) : "memory");
}
__device__ __forceinline__ void mbar_wait(uint32_t mbar, uint32_t phase) {
    uint32_t done = 0;
    while (!done)
        asm volatile("{\n\t.reg .pred p;\n\t"
                     "mbarrier.try_wait.parity.acquire.cta.shared::cta.b64 p, [%1], %2;\n\t"
                     "selp.b32 %0, 1, 0, p;\n\t}"
                     : "=r"(done) : "r"(mbar), "r"(phase) : "memory");
}

__global__ __launch_bounds__(288, 2)
void sim_gemm_tc(const char* __restrict__ cp_src, char* __restrict__ cp_dst) {
    extern __shared__ __align__(128) char smem[];
    const uint32_t sbase = (uint32_t)__cvta_generic_to_shared(smem);
    const uint32_t sb = sbase + 128;             // operand stages

    const int tid  = threadIdx.x;
    const int lane = tid & 31;
    const int by = blockIdx.y;                   // batch tile (0..3)
    const int bx = blockIdx.x;                   // class tile (0..156)

    if (tid == 0) {
#pragma unroll
        for (int m = 0; m < 6; m++)              // 2 operand + 4 copy mbars
            asm volatile("mbarrier.init.shared.b64 [%0], 1;"
                         :: "r"(sbase + m * 8) : "memory");
    }
    __syncthreads();                             // all 288 threads

    if (tid < 256) {
        // ================= compute warps 0-7 (R15-proven body) =================
        const int wid  = tid >> 5;
        const int wm   = wid & 1;
        const int wn   = wid >> 1;
        const int m_base = wm * 64;
        const int n_base = wn * 32;
        const int row0 = by * 128;
        const int col0 = bx * 128;

        const char* srcA  = (const char*)g_qh;
        const char* srcBh = (const char*)g_ph;
        const char* srcBl = (const char*)g_pl;

        auto fill = [&](int s, int ck) {
            const uint32_t mb = sbase + s * 8;
            const uint32_t d  = sb + s * STAGE_B;
            mbar_expect(mb, STAGE_B);
            bulk_g2s(d,               srcA  + tco(by, ck), CHUNK_B, mb);
            bulk_g2s(d + CHUNK_B,     srcBh + tco(bx, ck), CHUNK_B, mb);
            bulk_g2s(d + 2 * CHUNK_B, srcBl + tco(bx, ck), CHUNK_B, mb);
        };

        if (tid == 0) { fill(0, 0); fill(1, 1); }

        const int rA = (lane & 7) + ((lane >> 3) & 1) * 8;
        const int hA = ((lane >> 4) & 1) * 16;
        const int rB = (lane & 7) + ((lane >> 4) & 1) * 8;
        const int hB = ((lane >> 3) & 1) * 16;

        float4 acc[4][4];
#pragma unroll
        for (int i = 0; i < 4; i++)
#pragma unroll
            for (int j = 0; j < 4; j++) acc[i][j] = make_float4(0.f, 0.f, 0.f, 0.f);

        for (int kt = 0; kt < NCHUNK; kt++) {
            const int s = kt & 1;
            mbar_wait(sbase + s * 8, (kt >> 1) & 1);

            const uint32_t bAh = sb + s * STAGE_B;
            const uint32_t bBh = bAh + CHUNK_B;
            const uint32_t bBl = bAh + 2 * CHUNK_B;
#pragma unroll
            for (int kk = 0; kk < 4; kk++) {
                uint32_t Ah[4][4], Bh[2][4], Bl[2][4];
#pragma unroll
                for (int im = 0; im < 4; im++) {
                    uint32_t b = (uint32_t)((m_base + im * 16 + rA) * 128 + kk * 32 + hA);
                    LDSM4(Ah[im][0], Ah[im][1], Ah[im][2], Ah[im][3], bAh + sw128(b));
                }
#pragma unroll
                for (int t2 = 0; t2 < 2; t2++) {
                    uint32_t b = (uint32_t)((n_base + t2 * 16 + rB) * 128 + kk * 32 + hB);
                    LDSM4(Bh[t2][0], Bh[t2][1], Bh[t2][2], Bh[t2][3], bBh + sw128(b));
                    LDSM4(Bl[t2][0], Bl[t2][1], Bl[t2][2], Bl[t2][3], bBl + sw128(b));
                }
#pragma unroll
                for (int im = 0; im < 4; im++)
#pragma unroll
                    for (int in = 0; in < 4; in++)
                        MMAF16(acc[im][in], Ah[im], Bh[in >> 1][(in & 1) * 2],
                               Bh[in >> 1][(in & 1) * 2 + 1]);
#pragma unroll
                for (int im = 0; im < 4; im++)
#pragma unroll
                    for (int in = 0; in < 4; in++)
                        MMAF16(acc[im][in], Ah[im], Bl[in >> 1][(in & 1) * 2],
                               Bl[in >> 1][(in & 1) * 2 + 1]);
            }
            BAR_MMA();                            // compute warps done with stage s
            if (tid == 0 && kt + 2 < NCHUNK) fill(s, kt + 2);
        }

        // epilogue: scale by invp[col]/64, write g_sim
        const int gq = lane >> 2;
        const int qp = (lane & 3) * 2;
#pragma unroll
        for (int im = 0; im < 4; im++) {
            const int r = row0 + m_base + im * 16 + gq;
            float* row_ptr0 = g_sim + (size_t)r * C_;
            float* row_ptr1 = g_sim + (size_t)(r + 8) * C_;
#pragma unroll
            for (int in = 0; in < 4; in++) {
                const int c = col0 + n_base + in * 8 + qp;
                if (c < C_) {
                    const float ip0 = g_invp[c] * BINV;
                    const float ip1 = g_invp[c + 1] * BINV;
                    float4 a = acc[im][in];
                    float2 lo = make_float2(a.x * ip0, a.y * ip1);
                    float2 hi = make_float2(a.z * ip0, a.w * ip1);
                    *(float2*)(row_ptr0 + c) = lo;
                    *(float2*)(row_ptr1 + c) = hi;
                }
            }
        }
    } else if (tid == 256) {
        // ===== copy warp: pipelined part-bank stream (4 buffers, depth 2) ======
        const uint32_t stg0 = sbase + STG_OFF;
        const int cta = by * gridDim.x + bx;     // 0..627
        const long long j0 = (long long)cta * NCPY;
        int n = NCPY;
        if (j0 * CPYB >= PBYTES) n = 0;
        else if ((j0 + n) * CPYB > PBYTES) n = (int)(PBYTES / CPYB - j0);

        // prologue: prefetch chunks 0,1
        for (int p = 0; p < 2 && p < n; p++) {
            const uint32_t mb = sbase + 16 + p * 8;
            mbar_expect(mb, CPYB);
            bulk_g2s(stg0 + p * CPYB, cp_src + (j0 + p) * CPYB, CPYB, mb);
        }
        for (int i = 0; i < n; i++) {
            if (i + 2 < n) {
                if (i >= 2)   // buf (i+2)&3 was s2g'd at i-2; <=1 outstanding => done
                    asm volatile("cp.async.bulk.wait_group 1;" ::: "memory");
                const int b4 = (i + 2) & 3;
                const uint32_t mb = sbase + 16 + b4 * 8;
                mbar_expect(mb, CPYB);
                bulk_g2s(stg0 + b4 * CPYB, cp_src + (j0 + i + 2) * CPYB, CPYB, mb);
            }
            const int b4 = i & 3;
            mbar_wait(sbase + 16 + b4 * 8, (i >> 2) & 1);
            bulk_s2g(cp_dst + (j0 + i) * CPYB, stg0 + b4 * CPYB, CPYB);
            asm volatile("cp.async.bulk.commit_group;" ::: "memory");
        }
        asm volatile("cp.async.bulk.wait_group 0;" ::: "memory");
    }
}

// ---------------- 6: top-16 negatives + logsumexp per row ----------------
__global__ __launch_bounds__(256)
void topk_lse() {
    __shared__ float cand[256 * NHN];
    const int b = blockIdx.x;
    const int tid = threadIdx.x;
    const int lab = g_lab[b];
    const float* row = g_sim + (size_t)b * C_;

    float lt[NHN];
#pragma unroll
    for (int i = 0; i < NHN; i++) lt[i] = -1e30f;

    const float4* row4 = (const float4*)row;
    for (int c4 = tid; c4 < C_ / 4; c4 += 256) {
        float4 v4 = row4[c4];
        const int cb = c4 * 4;
        float vv[4] = {v4.x, v4.y, v4.z, v4.w};
#pragma unroll
        for (int j = 0; j < 4; j++) {
            if (cb + j == lab) continue;
            float v = vv[j];
            if (v > lt[NHN - 1]) {
                int k = NHN - 1;
                while (k > 0 && lt[k - 1] < v) { lt[k] = lt[k - 1]; --k; }
                lt[k] = v;
            }
        }
    }
#pragma unroll
    for (int i = 0; i < NHN; i++) cand[tid * NHN + i] = lt[i];

    for (int s = 128; s >= 1; s >>= 1) {
        __syncthreads();
        if (tid < s) {
            const float* Aa = cand + tid * NHN;
            const float* Bb = cand + (tid + s) * NHN;
            float out[NHN];
            int i = 0, j = 0;
#pragma unroll
            for (int t = 0; t < NHN; t++) {
                float a = Aa[i], bv = Bb[j];
                if (a >= bv) { out[t] = a; i++; } else { out[t] = bv; j++; }
            }
#pragma unroll
            for (int t = 0; t < NHN; t++) cand[tid * NHN + t] = out[t];
        }
    }
    __syncthreads();
    if (tid == 0) {
        float pos = row[lab];
        float mx = pos;
#pragma unroll
        for (int i = 0; i < NHN; i++) mx = fmaxf(mx, cand[i]);
        float sum = __expf(pos - mx);
#pragma unroll
        for (int i = 0; i < NHN; i++) sum += __expf(cand[i] - mx);
        g_nce[b] = mx + logf(sum) - pos;
    }
}

// ---------------- 7: alignment loss per row ----------------
__global__ __launch_bounds__(256)
void align_row(const float* __restrict__ emb, const float* __restrict__ sat,
               const float* __restrict__ neb) {
    __shared__ float red[5][8];
    const int b = blockIdx.x;
    const int tid = threadIdx.x;
    const int lab = g_lab[b];
    const float* e = emb + (size_t)b * DE;
    const float* s = sat + (size_t)b * DE;
    const float* p = neb + (size_t)lab * DE;
    float ee = 0, ss = 0, pp = 0, ep = 0, sp = 0;
    for (int i = tid; i < DE; i += 256) {
        float ev = e[i], sv = s[i], pv = p[i];
        ee += ev * ev; ss += sv * sv; pp += pv * pv;
        ep += ev * pv; sp += sv * pv;
    }
#pragma unroll
    for (int o = 16; o; o >>= 1) {
        ee += __shfl_xor_sync(0xffffffffu, ee, o);
        ss += __shfl_xor_sync(0xffffffffu, ss, o);
        pp += __shfl_xor_sync(0xffffffffu, pp, o);
        ep += __shfl_xor_sync(0xffffffffu, ep, o);
        sp += __shfl_xor_sync(0xffffffffu, sp, o);
    }
    int w = tid >> 5;
    if ((tid & 31) == 0) {
        red[0][w] = ee; red[1][w] = ss; red[2][w] = pp; red[3][w] = ep; red[4][w] = sp;
    }
    __syncthreads();
    if (tid == 0) {
        float a0 = 0, a1 = 0, a2 = 0, a3 = 0, a4 = 0;
        for (int i = 0; i < 8; i++) {
            a0 += red[0][i]; a1 += red[1][i]; a2 += red[2][i];
            a3 += red[3][i]; a4 += red[4][i];
        }
        float dn = fmaxf(sqrtf(a0), 1e-12f);
        float sn = fmaxf(sqrtf(a1), 1e-12f);
        float pn = fmaxf(sqrtf(a2), 1e-12f);
        g_align[b] = 0.5f * ((1.0f - a3 / (dn * pn)) + (1.0f - a4 / (sn * pn)));
    }
}

// ---------------- 8: final scalar reduction ----------------
__global__ __launch_bounds__(512)
void finalize(float* __restrict__ out_loss) {
    __shared__ float s1[512], s2[512];
    int t = threadIdx.x;
    s1[t] = g_nce[t];
    s2[t] = g_align[t];
    __syncthreads();
    for (int s = 256; s >= 1; s >>= 1) {
        if (t < s) { s1[t] += s1[t + s]; s2[t] += s2[t + s]; }
        __syncthreads();
    }
    if (t == 0) {
        out_loss[0] = s1[0] / (float)B_;
        out_loss[1] = s2[0] / (float)B_;
    }
}

// ---------------- launch ----------------
extern "C" void kernel_launch(void* const* d_in, const int* in_sizes, int n_in,
                              void* d_out, int out_size) {
    const float* pf    = (const float*)d_in[0];     // [512, 8, 256]
    const float* emb   = (const float*)d_in[1];     // [512, 512]
    const float* sat   = (const float*)d_in[2];     // [512, 512]
    const float* pbank = (const float*)d_in[3];     // [20000, 8, 256]
    const float* ebank = (const float*)d_in[4];     // [20000, 512]
    const int*   labs  = (const int*)d_in[5];       // [512] int32/int64 auto-detected

    const int P = in_sizes[3];   // 40,960,000
    const int E = in_sizes[4];   // 10,240,000

    float* out    = (float*)d_out;
    float* out_pb = out;
    float* out_eb = out + P;
    float* out_ls = out + P + E;

    static bool attr_done = false;
    if (!attr_done) {
        cudaFuncSetAttribute(sim_gemm_tc,
                             cudaFuncAttributeMaxDynamicSharedMemorySize, GEMM_SMEM);
        attr_done = true;
    }

    // 0. labels + inverse map
    clear_invmap<<<(C_ + 255) / 256, 256>>>();
    decode_labels<<<1, B_>>>(labs);
    // 1. fused embed copy + EMA + norms + fp16 splits (tiled layout) + q prep
    proto_fused<<<(C_ + B_ + 7) / 8, 256>>>(ebank, emb, out_eb);
    // 2. GEMM with pipelined warp-specialized part-bank copy
    dim3 ggrid(NTILE_C, B_ / 128);
    sim_gemm_tc<<<ggrid, 288, GEMM_SMEM>>>((const char*)pbank, (char*)out_pb);
    // 3. EMA fix-up on the 512 labeled part rows
    ema_part<<<B_, 256>>>(pf, pbank, out_pb);
    // 4. top-k + logsumexp
    topk_lse<<<B_, 256>>>();
    // 5. alignment
    align_row<<<B_, 256>>>(emb, sat, out_eb);
    // 6. finalize scalars
    finalize<<<1, 512>>>(out_ls);
}